// round 14
// baseline (speedup 1.0000x reference)
#include <cuda_runtime.h>
#include <cuda_fp16.h>
#include <math.h>

#define BATCH 1024
#define SEQ   512
#define HID   64
#define BC    16
#define NT    512
#define XS    72              // padded h/x row stride (halves)
#define NCHUNK (BATCH / BC)   // 64
#define PUB   8

__device__ __half g_h1[(size_t)BATCH * SEQ * HID];
__device__ int g_prog[NCHUNK];

__global__ void init_flags() {
    if (threadIdx.x < NCHUNK) g_prog[threadIdx.x] = 0;
}

__device__ __forceinline__ unsigned h2pack(float lo, float hi) {
    __half2 v = __floats2half2_rn(lo, hi);
    return reinterpret_cast<unsigned&>(v);
}

// m16n8k16 fp16 mma, fp32 accumulate.
__device__ __forceinline__ void mmah(float* d,
                                     unsigned a0, unsigned a1,
                                     unsigned a2, unsigned a3,
                                     unsigned b0, unsigned b1) {
    asm volatile(
        "mma.sync.aligned.m16n8k16.row.col.f32.f16.f16.f32 "
        "{%0,%1,%2,%3}, {%4,%5,%6,%7}, {%8,%9}, {%0,%1,%2,%3};"
        : "+f"(d[0]), "+f"(d[1]), "+f"(d[2]), "+f"(d[3])
        : "r"(a0), "r"(a1), "r"(a2), "r"(a3), "r"(b0), "r"(b1));
}

__device__ __forceinline__ float tanha(float x) {
    float r; asm("tanh.approx.f32 %0, %1;" : "=f"(r) : "f"(x)); return r;
}
__device__ __forceinline__ float sig_fast(float x) {
    return fmaf(tanha(0.5f * x), 0.5f, 0.5f);
}

__device__ __forceinline__ void wait_prog(const int* p, int need) {
    int v;
    do {
        asm volatile("ld.global.acquire.gpu.b32 %0, [%1];"
                     : "=r"(v) : "l"(p) : "memory");
    } while (v < need);
}

// Warp-specialized two-layer pipelined LSTM (fp16 tensor path).
// K-slot permutation: physical mma k-slots (2tg,2tg+1,2tg+8,2tg+9) carry
// logical k (4tg..4tg+3), so each A fragment row is ONE LDS.64 of 4
// contiguous halves; weight fragments use the same permutation. Exact.
// Split accumulators (kk 0-1 -> d, 2-3 -> e) halve the HMMA chain depth.
__global__ void __launch_bounds__(NT, 1) lstm2_kernel(
    const float* __restrict__ x,
    const float* __restrict__ wih0, const float* __restrict__ whh0,
    const float* __restrict__ bih0, const float* __restrict__ bhh0,
    const float* __restrict__ wih1, const float* __restrict__ whh1,
    const float* __restrict__ bih1, const float* __restrict__ bhh1,
    const float* __restrict__ fcw,  const float* __restrict__ fcb,
    float* __restrict__ out)
{
    __shared__ __align__(16) __half sh[2][BC * XS];   // h, double-buffered
    __shared__ __align__(16) __half sx[2][BC * XS];   // x_t, double-buffered
    // x-GEMM fp32 partials: [buf][wlo][nn(gate)][lane]
    __shared__ __align__(16) float4 sxp[2][8][4][32];

    const int tid  = threadIdx.x;
    const int w    = tid >> 5, lane = tid & 31;
    const int grp  = lane >> 2, tg = lane & 3;
    const int wlo  = w & 7;
    const bool isR = (w < 8);
    const int role  = (int)(blockIdx.x >> 6);
    const int chunk = (int)(blockIdx.x & 63);
    const int b0    = chunk * BC;

    // staging map (X warps): thread -> (batch row sb, 4 cols at sj)
    const int wt = tid & 255;
    const int sb = wt >> 4;
    const int sj = (wt & 15) * 4;

    const float* wih = role ? wih1 : wih0;
    const float* whh = role ? whh1 : whh0;
    const float* bih = role ? bih1 : bih0;
    const float* bhh = role ? bhh1 : bhh0;
    int* prog = &g_prog[chunk];

    // Gate-permuted fp16 weight fragments with k-slot permutation:
    // phys slots (2tg,2tg+1) <- logical k0+4tg, k0+4tg+1
    // phys slots (2tg+8,2tg+9) <- logical k0+4tg+2, k0+4tg+3
    const float* wsrc = isR ? whh : wih;
    unsigned bw[4][4][2];
#pragma unroll
    for (int kk = 0; kk < 4; kk++)
#pragma unroll
        for (int nn = 0; nn < 4; nn++) {
            const int n = nn * 64 + 8 * wlo + grp;
            const int k0 = 16 * kk + 4 * tg;
            bw[kk][nn][0] = h2pack(wsrc[n * HID + k0],     wsrc[n * HID + k0 + 1]);
            bw[kk][nn][1] = h2pack(wsrc[n * HID + k0 + 2], wsrc[n * HID + k0 + 3]);
        }

    // R-warp cell state & biases: cells (grp + 8rr, j0 + cc), j0 = 8wlo+2tg.
    const int j0 = 8 * wlo + 2 * tg;
    float bia[4][2];
#pragma unroll
    for (int g = 0; g < 4; g++) {
        bia[g][0] = bih[g * 64 + j0]     + bhh[g * 64 + j0];
        bia[g][1] = bih[g * 64 + j0 + 1] + bhh[g * 64 + j0 + 1];
    }
    float cst[2][2] = {{0.f, 0.f}, {0.f, 0.f}};

    // ── prologue: zero both h buffers; stage x(0), x(1); pre-GEMM x(0).
    for (int i = tid; i < 2 * BC * XS / 2; i += NT) ((unsigned*)sh)[i] = 0u;
    if (!isR) {
        if (role) wait_prog(prog, 2);
#pragma unroll
        for (int tt = 0; tt < 2; tt++) {
            uint2 r;
            if (role == 0) {
                const float4 v = *(const float4*)&x[((size_t)(b0 + sb) * SEQ + tt) * HID + sj];
                r.x = h2pack(v.x, v.y);
                r.y = h2pack(v.z, v.w);
            } else {
                r = *(const uint2*)&g_h1[((size_t)(b0 + sb) * SEQ + tt) * HID + sj];
            }
            *(uint2*)&sx[tt][sb * XS + sj] = r;
        }
    }
    __syncthreads();

    // X-warp GEMM: sx[buf] @ w_ih -> sxp[buf]. LDS.64 frags, split accum.
#define XGEMM(buf)                                                            \
    {                                                                         \
        float d[4][4], e[4][4];                                               \
        _Pragma("unroll")                                                     \
        for (int nn = 0; nn < 4; nn++)                                        \
            _Pragma("unroll")                                                 \
            for (int i = 0; i < 4; i++) { d[nn][i] = 0.0f; e[nn][i] = 0.0f; } \
        _Pragma("unroll")                                                     \
        for (int kk = 0; kk < 4; kk++) {                                      \
            const int ko = 16 * kk + 4 * tg;                                  \
            const uint2 va = *(const uint2*)&sx[buf][grp * XS + ko];          \
            const uint2 vb = *(const uint2*)&sx[buf][(grp + 8) * XS + ko];    \
            float* acc = (kk < 2) ? &d[0][0] : &e[0][0];                      \
            _Pragma("unroll")                                                 \
            for (int nn = 0; nn < 4; nn++)                                    \
                mmah(acc + 4 * nn, va.x, vb.x, va.y, vb.y,                    \
                     bw[kk][nn][0], bw[kk][nn][1]);                           \
        }                                                                     \
        _Pragma("unroll")                                                     \
        for (int nn = 0; nn < 4; nn++)                                        \
            sxp[buf][wlo][nn][lane] =                                         \
                make_float4(d[nn][0] + e[nn][0], d[nn][1] + e[nn][1],         \
                            d[nn][2] + e[nn][2], d[nn][3] + e[nn][3]);        \
    }

    if (!isR) XGEMM(0);
    __syncthreads();

    for (int t = 0; t < SEQ; t++) {
        const int cur = t & 1, nb = cur ^ 1;

        if (isR) {
            // ── R: d <- x-partials; split h@w_hh over d (kk 0-1) / e (2-3).
            float d[4][4], e[4][4];
#pragma unroll
            for (int nn = 0; nn < 4; nn++) {
                const float4 v = sxp[cur][wlo][nn][lane];
                d[nn][0] = v.x; d[nn][1] = v.y; d[nn][2] = v.z; d[nn][3] = v.w;
#pragma unroll
                for (int i = 0; i < 4; i++) e[nn][i] = 0.0f;
            }
#pragma unroll
            for (int kk = 0; kk < 4; kk++) {
                const int ko = 16 * kk + 4 * tg;
                const uint2 va = *(const uint2*)&sh[cur][grp * XS + ko];
                const uint2 vb = *(const uint2*)&sh[cur][(grp + 8) * XS + ko];
                float* acc = (kk < 2) ? &d[0][0] : &e[0][0];
#pragma unroll
                for (int nn = 0; nn < 4; nn++)
                    mmah(acc + 4 * nn, va.x, vb.x, va.y, vb.y,
                         bw[kk][nn][0], bw[kk][nn][1]);
            }

            // ── register-resident cell update: 4 cells/thread.
#pragma unroll
            for (int rr = 0; rr < 2; rr++) {
                float h2[2];
#pragma unroll
                for (int cc = 0; cc < 2; cc++) {
                    const int di = 2 * rr + cc;
                    const float iv = sig_fast(d[0][di] + e[0][di] + bia[0][cc]);
                    const float fv = sig_fast(d[1][di] + e[1][di] + bia[1][cc]);
                    const float gv = tanha(d[2][di] + e[2][di] + bia[2][cc]);
                    const float ov = sig_fast(d[3][di] + e[3][di] + bia[3][cc]);
                    float& cr = cst[rr][cc];
                    cr = fv * cr + iv * gv;
                    h2[cc] = ov * tanha(cr);
                }
                const int row = grp + 8 * rr;
                const unsigned hp = h2pack(h2[0], h2[1]);
                *(unsigned*)&sh[nb][row * XS + j0] = hp;
                if (role == 0)
                    *(unsigned*)&g_h1[((size_t)(b0 + row) * SEQ + t) * HID + j0] = hp;
            }
        } else {
            // ── X: poll (consumer), prefetch x(t+2), GEMM x(t+1), stage.
            if (role && (t & (PUB - 1)) == 0) {
                int need = t + PUB + 2; if (need > SEQ) need = SEQ;
                wait_prog(prog, need);
            }
            uint2 r;
            if (t + 2 < SEQ) {
                if (role == 0) {
                    const float4 v = *(const float4*)&x[((size_t)(b0 + sb) * SEQ + (t + 2)) * HID + sj];
                    r.x = h2pack(v.x, v.y);
                    r.y = h2pack(v.z, v.w);
                } else {
                    r = *(const uint2*)&g_h1[((size_t)(b0 + sb) * SEQ + (t + 2)) * HID + sj];
                }
            }
            if (t + 1 < SEQ) XGEMM(nb);
            if (t + 2 < SEQ)
                *(uint2*)&sx[cur][sb * XS + sj] = r;
        }

        // ── publish: R threads drain h1 STGs before the barrier.
        const bool pub = (role == 0) && (((t + 1) & (PUB - 1)) == 0);
        if (pub && isR) __threadfence();
        __syncthreads();
        if (pub && tid == 0)
            asm volatile("st.global.relaxed.gpu.b32 [%0], %1;"
                         :: "l"(prog), "r"(t + 1) : "memory");
    }

    // Fused FC head (layer-1 CTAs): final h is in sh[0].
    if (role == 1) {
        float v = fcw[lane] * __half2float(sh[0][w * XS + lane])
                + fcw[lane + 32] * __half2float(sh[0][w * XS + lane + 32]);
#pragma unroll
        for (int off = 16; off; off >>= 1)
            v += __shfl_down_sync(0xffffffffu, v, off);
        if (lane == 0) out[b0 + w] = v + fcb[0];
    }
#undef XGEMM
}

extern "C" void kernel_launch(void* const* d_in, const int* in_sizes, int n_in,
                              void* d_out, int out_size)
{
    const float* x     = (const float*)d_in[0];
    const float* w_ih0 = (const float*)d_in[1];
    const float* w_hh0 = (const float*)d_in[2];
    const float* b_ih0 = (const float*)d_in[3];
    const float* b_hh0 = (const float*)d_in[4];
    const float* w_ih1 = (const float*)d_in[5];
    const float* w_hh1 = (const float*)d_in[6];
    const float* b_ih1 = (const float*)d_in[7];
    const float* b_hh1 = (const float*)d_in[8];
    const float* fc_w  = (const float*)d_in[9];
    const float* fc_b  = (const float*)d_in[10];
    float* out = (float*)d_out;

    init_flags<<<1, 64>>>();
    lstm2_kernel<<<2 * NCHUNK, NT>>>(x,
                                     w_ih0, w_hh0, b_ih0, b_hh0,
                                     w_ih1, w_hh1, b_ih1, b_hh1,
                                     fc_w, fc_b, out);
}

// round 15
// speedup vs baseline: 1.1069x; 1.1069x over previous
#include <cuda_runtime.h>
#include <cuda_fp16.h>
#include <math.h>

#define BATCH 1024
#define SEQ   512
#define HID   64
#define BC    16
#define NT    512
#define XS    72              // padded h/x row stride (halves): conflict-free
#define NCHUNK (BATCH / BC)   // 64
#define PUB   8

__device__ __half g_h1[(size_t)BATCH * SEQ * HID];
__device__ int g_prog[NCHUNK];

__global__ void init_flags() {
    if (threadIdx.x < NCHUNK) g_prog[threadIdx.x] = 0;
}

__device__ __forceinline__ unsigned h2pack(float lo, float hi) {
    __half2 v = __floats2half2_rn(lo, hi);
    return reinterpret_cast<unsigned&>(v);
}

// m16n8k16 fp16 mma, fp32 accumulate.
__device__ __forceinline__ void mmah(float* d,
                                     unsigned a0, unsigned a1,
                                     unsigned a2, unsigned a3,
                                     unsigned b0, unsigned b1) {
    asm volatile(
        "mma.sync.aligned.m16n8k16.row.col.f32.f16.f16.f32 "
        "{%0,%1,%2,%3}, {%4,%5,%6,%7}, {%8,%9}, {%0,%1,%2,%3};"
        : "+f"(d[0]), "+f"(d[1]), "+f"(d[2]), "+f"(d[3])
        : "r"(a0), "r"(a1), "r"(a2), "r"(a3), "r"(b0), "r"(b1));
}

__device__ __forceinline__ float tanha(float x) {
    float r; asm("tanh.approx.f32 %0, %1;" : "=f"(r) : "f"(x)); return r;
}
__device__ __forceinline__ float sig_fast(float x) {
    return fmaf(tanha(0.5f * x), 0.5f, 0.5f);
}

__device__ __forceinline__ void wait_prog(const int* p, int need) {
    int v;
    do {
        asm volatile("ld.global.acquire.gpu.b32 %0, [%1];"
                     : "=r"(v) : "l"(p) : "memory");
    } while (v < need);
}

// Warp-specialized two-layer pipelined LSTM, fp16 tensor path (R12 base).
// grid=128: role 0 = layer 0 (producer), role 1 = layer 1 (consumer + FC).
//   warps 0-7  ("R"): h(t) @ w_hh via m16n8k16 mma (reads sh[cur]),
//                     register-resident cell update, writes sh[nb] + g_h1.
//   warps 8-15 ("X"): x(t+1) @ w_ih -> sxp[nb]; DEEP-STAGED input loads:
//                     LDG for x(t+3) issued at step t, held in a register
//                     across a full step, stored to sx at step t+1 — the
//                     DRAM/L2 latency gets a whole step of cover instead
//                     of one XGEMM (the R12 X-path exposure).
// One __syncthreads per step; all hand-offs double-buffered across it.
__global__ void __launch_bounds__(NT, 1) lstm2_kernel(
    const float* __restrict__ x,
    const float* __restrict__ wih0, const float* __restrict__ whh0,
    const float* __restrict__ bih0, const float* __restrict__ bhh0,
    const float* __restrict__ wih1, const float* __restrict__ whh1,
    const float* __restrict__ bih1, const float* __restrict__ bhh1,
    const float* __restrict__ fcw,  const float* __restrict__ fcb,
    float* __restrict__ out)
{
    __shared__ __align__(16) __half sh[2][BC * XS];   // h, double-buffered
    __shared__ __align__(16) __half sx[2][BC * XS];   // x_t, double-buffered
    // x-GEMM fp32 partials: [buf][wlo][nn(gate)][row 0..15][col 0..7]
    __shared__ __align__(16) float sxp[2][8][4][16][8];

    const int tid  = threadIdx.x;
    const int w    = tid >> 5, lane = tid & 31;
    const int grp  = lane >> 2, tg = lane & 3;
    const int wlo  = w & 7;
    const bool isR = (w < 8);
    const int role  = (int)(blockIdx.x >> 6);
    const int chunk = (int)(blockIdx.x & 63);
    const int b0    = chunk * BC;

    // staging map (X warps): thread -> (batch row sb, 4 cols at sj)
    const int wt = tid & 255;
    const int sb = wt >> 4;
    const int sj = (wt & 15) * 4;

    const float* wih = role ? wih1 : wih0;
    const float* whh = role ? whh1 : whh0;
    const float* bih = role ? bih1 : bih0;
    const float* bhh = role ? bhh1 : bhh0;
    int* prog = &g_prog[chunk];

    // Gate-permuted fp16 weight fragments: tile nn == gate nn.
    const float* wsrc = isR ? whh : wih;
    unsigned bw[4][4][2];
#pragma unroll
    for (int kk = 0; kk < 4; kk++)
#pragma unroll
        for (int nn = 0; nn < 4; nn++) {
            const int n = nn * 64 + 8 * wlo + grp;
            const int k0 = 16 * kk + 2 * tg;
            bw[kk][nn][0] = h2pack(wsrc[n * HID + k0],     wsrc[n * HID + k0 + 1]);
            bw[kk][nn][1] = h2pack(wsrc[n * HID + k0 + 8], wsrc[n * HID + k0 + 9]);
        }

    // R-warp cell state & biases: cells (grp + 8rr, j0 + cc), j0 = 8wlo+2tg.
    const int j0 = 8 * wlo + 2 * tg;
    float bia[4][2];
#pragma unroll
    for (int g = 0; g < 4; g++) {
        bia[g][0] = bih[g * 64 + j0]     + bhh[g * 64 + j0];
        bia[g][1] = bih[g * 64 + j0 + 1] + bhh[g * 64 + j0 + 1];
    }
    float cst[2][2] = {{0.f, 0.f}, {0.f, 0.f}};

    // Deep-staged input load helper.
#define XLOAD(r, tt)                                                          \
    {                                                                         \
        if (role == 0) {                                                      \
            const float4 v = *(const float4*)&x[((size_t)(b0 + sb) * SEQ + (tt)) * HID + sj]; \
            (r).x = h2pack(v.x, v.y);                                         \
            (r).y = h2pack(v.z, v.w);                                         \
        } else {                                                              \
            (r) = *(const uint2*)&g_h1[((size_t)(b0 + sb) * SEQ + (tt)) * HID + sj]; \
        }                                                                     \
    }

    // ── prologue: zero h; stage x(0), x(1); preload x(2); pre-GEMM x(0).
    for (int i = tid; i < 2 * BC * XS / 2; i += NT) ((unsigned*)sh)[i] = 0u;
    uint2 rp;                           // staged value for x(t+2), X warps
    if (!isR) {
        if (role) wait_prog(prog, 3);
#pragma unroll
        for (int tt = 0; tt < 2; tt++) {
            uint2 r;
            XLOAD(r, tt);
            *(uint2*)&sx[tt][sb * XS + sj] = r;
        }
        XLOAD(rp, 2);
    }
    __syncthreads();

    // X-warp GEMM macro: sx[buf] @ w_ih -> sxp[buf].
#define XGEMM(buf)                                                            \
    {                                                                         \
        float d[4][4];                                                        \
        _Pragma("unroll")                                                     \
        for (int nn = 0; nn < 4; nn++)                                        \
            _Pragma("unroll")                                                 \
            for (int i = 0; i < 4; i++) d[nn][i] = 0.0f;                      \
        _Pragma("unroll")                                                     \
        for (int kk = 0; kk < 4; kk++) {                                      \
            const int ko = 16 * kk + 2 * tg;                                  \
            const unsigned a0 = *(const unsigned*)&sx[buf][grp * XS + ko];    \
            const unsigned a1 = *(const unsigned*)&sx[buf][(grp + 8) * XS + ko]; \
            const unsigned a2 = *(const unsigned*)&sx[buf][grp * XS + ko + 8]; \
            const unsigned a3 = *(const unsigned*)&sx[buf][(grp + 8) * XS + ko + 8]; \
            _Pragma("unroll")                                                 \
            for (int nn = 0; nn < 4; nn++)                                    \
                mmah(d[nn], a0, a1, a2, a3, bw[kk][nn][0], bw[kk][nn][1]);    \
        }                                                                     \
        _Pragma("unroll")                                                     \
        for (int nn = 0; nn < 4; nn++) {                                      \
            *(float2*)&sxp[buf][wlo][nn][grp][2 * tg]     = make_float2(d[nn][0], d[nn][1]); \
            *(float2*)&sxp[buf][wlo][nn][grp + 8][2 * tg] = make_float2(d[nn][2], d[nn][3]); \
        }                                                                     \
    }

    if (!isR) XGEMM(0);
    __syncthreads();

    for (int t = 0; t < SEQ; t++) {
        const int cur = t & 1, nb = cur ^ 1;

        if (isR) {
            // ── R: init accumulators with x-partials, add h @ w_hh.
            float d[4][4];
#pragma unroll
            for (int nn = 0; nn < 4; nn++) {
                const float2 lo = *(const float2*)&sxp[cur][wlo][nn][grp][2 * tg];
                const float2 hi = *(const float2*)&sxp[cur][wlo][nn][grp + 8][2 * tg];
                d[nn][0] = lo.x; d[nn][1] = lo.y; d[nn][2] = hi.x; d[nn][3] = hi.y;
            }
#pragma unroll
            for (int kk = 0; kk < 4; kk++) {
                const int ko = 16 * kk + 2 * tg;
                const unsigned a0 = *(const unsigned*)&sh[cur][grp * XS + ko];
                const unsigned a1 = *(const unsigned*)&sh[cur][(grp + 8) * XS + ko];
                const unsigned a2 = *(const unsigned*)&sh[cur][grp * XS + ko + 8];
                const unsigned a3 = *(const unsigned*)&sh[cur][(grp + 8) * XS + ko + 8];
#pragma unroll
                for (int nn = 0; nn < 4; nn++)
                    mmah(d[nn], a0, a1, a2, a3, bw[kk][nn][0], bw[kk][nn][1]);
            }
            // ── register-resident cell update: 4 cells/thread.
#pragma unroll
            for (int rr = 0; rr < 2; rr++) {
                float h2[2];
#pragma unroll
                for (int cc = 0; cc < 2; cc++) {
                    const int di = 2 * rr + cc;
                    const float iv = sig_fast(d[0][di] + bia[0][cc]);
                    const float fv = sig_fast(d[1][di] + bia[1][cc]);
                    const float gv = tanha(d[2][di] + bia[2][cc]);
                    const float ov = sig_fast(d[3][di] + bia[3][cc]);
                    float& cr = cst[rr][cc];
                    cr = fv * cr + iv * gv;
                    h2[cc] = ov * tanha(cr);
                }
                const int row = grp + 8 * rr;
                const unsigned hp = h2pack(h2[0], h2[1]);
                *(unsigned*)&sh[nb][row * XS + j0] = hp;
                if (role == 0)
                    *(unsigned*)&g_h1[((size_t)(b0 + row) * SEQ + t) * HID + j0] = hp;
            }
        } else {
            // ── X: poll (consumer), issue LDG x(t+3), GEMM x(t+1),
            //      store the step-old staged value x(t+2).
            if (role && (t & (PUB - 1)) == 0) {
                int need = t + PUB + 3; if (need > SEQ) need = SEQ;
                wait_prog(prog, need);
            }
            uint2 rN;
            if (t + 3 < SEQ) XLOAD(rN, t + 3);
            if (t + 1 < SEQ) XGEMM(nb);
            if (t + 2 < SEQ)
                *(uint2*)&sx[cur][sb * XS + sj] = rp;
            rp = rN;
        }

        // ── publish: R threads drain h1 STGs before the barrier.
        const bool pub = (role == 0) && (((t + 1) & (PUB - 1)) == 0);
        if (pub && isR) __threadfence();
        __syncthreads();
        if (pub && tid == 0)
            asm volatile("st.global.relaxed.gpu.b32 [%0], %1;"
                         :: "l"(prog), "r"(t + 1) : "memory");
    }

    // Fused FC head (layer-1 CTAs): final h is in sh[0].
    if (role == 1) {
        float v = fcw[lane] * __half2float(sh[0][w * XS + lane])
                + fcw[lane + 32] * __half2float(sh[0][w * XS + lane + 32]);
#pragma unroll
        for (int off = 16; off; off >>= 1)
            v += __shfl_down_sync(0xffffffffu, v, off);
        if (lane == 0) out[b0 + w] = v + fcb[0];
    }
#undef XGEMM
#undef XLOAD
}

extern "C" void kernel_launch(void* const* d_in, const int* in_sizes, int n_in,
                              void* d_out, int out_size)
{
    const float* x     = (const float*)d_in[0];
    const float* w_ih0 = (const float*)d_in[1];
    const float* w_hh0 = (const float*)d_in[2];
    const float* b_ih0 = (const float*)d_in[3];
    const float* b_hh0 = (const float*)d_in[4];
    const float* w_ih1 = (const float*)d_in[5];
    const float* w_hh1 = (const float*)d_in[6];
    const float* b_ih1 = (const float*)d_in[7];
    const float* b_hh1 = (const float*)d_in[8];
    const float* fc_w  = (const float*)d_in[9];
    const float* fc_b  = (const float*)d_in[10];
    float* out = (float*)d_out;

    init_flags<<<1, 64>>>();
    lstm2_kernel<<<2 * NCHUNK, NT>>>(x,
                                     w_ih0, w_hh0, b_ih0, b_hh0,
                                     w_ih1, w_hh1, b_ih1, b_hh1,
                                     fc_w, fc_b, out);
}

// round 17
// speedup vs baseline: 1.1517x; 1.0405x over previous
#include <cuda_runtime.h>
#include <cuda_fp16.h>
#include <math.h>

#define BATCH 1024
#define SEQ   512
#define HID   64
#define BC    16
#define NT    512
#define XS    72              // padded h/x row stride (halves): conflict-free
#define NCHUNK (BATCH / BC)   // 64
#define PUB   8

__device__ __half g_h1[(size_t)BATCH * SEQ * HID];
__device__ int g_prog[NCHUNK];

__global__ void init_flags() {
    if (threadIdx.x < NCHUNK) g_prog[threadIdx.x] = 0;
}

__device__ __forceinline__ unsigned h2pack(float lo, float hi) {
    __half2 v = __floats2half2_rn(lo, hi);
    return reinterpret_cast<unsigned&>(v);
}

// m16n8k16 fp16 mma, fp32 accumulate.
__device__ __forceinline__ void mmah(float* d,
                                     unsigned a0, unsigned a1,
                                     unsigned a2, unsigned a3,
                                     unsigned b0, unsigned b1) {
    asm volatile(
        "mma.sync.aligned.m16n8k16.row.col.f32.f16.f16.f32 "
        "{%0,%1,%2,%3}, {%4,%5,%6,%7}, {%8,%9}, {%0,%1,%2,%3};"
        : "+f"(d[0]), "+f"(d[1]), "+f"(d[2]), "+f"(d[3])
        : "r"(a0), "r"(a1), "r"(a2), "r"(a3), "r"(b0), "r"(b1));
}

// fp32 MUFU.TANH activations — the precision floor (f16x2 variants exceed
// the 1e-3 budget; measured R16).
__device__ __forceinline__ float tanha(float x) {
    float r; asm("tanh.approx.f32 %0, %1;" : "=f"(r) : "f"(x)); return r;
}
__device__ __forceinline__ float sig_fast(float x) {
    return fmaf(tanha(0.5f * x), 0.5f, 0.5f);
}

__device__ __forceinline__ void wait_prog(const int* p, int need) {
    int v;
    do {
        asm volatile("ld.global.acquire.gpu.b32 %0, [%1];"
                     : "=r"(v) : "l"(p) : "memory");
    } while (v < need);
}

// Warp-specialized two-layer pipelined LSTM, fp16 tensor path (R12 base,
// float4/lane sxp hand-off). grid=128: role 0 = layer 0 (producer),
// role 1 = layer 1 (consumer + FC head). Per CTA (512 thr):
//   warps 0-7  ("R"): h(t) @ w_hh via m16n8k16 mma (reads sh[cur]),
//                     register-resident fp32 cell update, writes sh[nb]
//                     (fp16) + g_h1 (fp16, producer only).
//   warps 8-15 ("X"): x(t+1) @ w_ih -> sxp[nb] (one float4 per lane — X
//                     thread (wlo,lane) produces exactly the fragment R
//                     thread (wlo,lane) consumes); stages x(t+2) into sx;
//                     consumer-side progress polling.
// One __syncthreads per step; all hand-offs double-buffered across it.
__global__ void __launch_bounds__(NT, 1) lstm2_kernel(
    const float* __restrict__ x,
    const float* __restrict__ wih0, const float* __restrict__ whh0,
    const float* __restrict__ bih0, const float* __restrict__ bhh0,
    const float* __restrict__ wih1, const float* __restrict__ whh1,
    const float* __restrict__ bih1, const float* __restrict__ bhh1,
    const float* __restrict__ fcw,  const float* __restrict__ fcb,
    float* __restrict__ out)
{
    __shared__ __align__(16) __half sh[2][BC * XS];   // h, double-buffered
    __shared__ __align__(16) __half sx[2][BC * XS];   // x_t, double-buffered
    // x-GEMM fp32 partials: [buf][wlo][nn(gate)][lane] = d[nn][0..3]
    __shared__ __align__(16) float4 sxp[2][8][4][32];

    const int tid  = threadIdx.x;
    const int w    = tid >> 5, lane = tid & 31;
    const int grp  = lane >> 2, tg = lane & 3;
    const int wlo  = w & 7;
    const bool isR = (w < 8);
    const int role  = (int)(blockIdx.x >> 6);
    const int chunk = (int)(blockIdx.x & 63);
    const int b0    = chunk * BC;

    // staging map (X warps): thread -> (batch row sb, 4 cols at sj)
    const int wt = tid & 255;
    const int sb = wt >> 4;
    const int sj = (wt & 15) * 4;

    const float* wih = role ? wih1 : wih0;
    const float* whh = role ? whh1 : whh0;
    const float* bih = role ? bih1 : bih0;
    const float* bhh = role ? bhh1 : bhh0;
    int* prog = &g_prog[chunk];

    // Gate-permuted fp16 weight fragments: tile nn == gate nn.
    const float* wsrc = isR ? whh : wih;
    unsigned bw[4][4][2];
#pragma unroll
    for (int kk = 0; kk < 4; kk++)
#pragma unroll
        for (int nn = 0; nn < 4; nn++) {
            const int n = nn * 64 + 8 * wlo + grp;
            const int k0 = 16 * kk + 2 * tg;
            bw[kk][nn][0] = h2pack(wsrc[n * HID + k0],     wsrc[n * HID + k0 + 1]);
            bw[kk][nn][1] = h2pack(wsrc[n * HID + k0 + 8], wsrc[n * HID + k0 + 9]);
        }

    // R-warp cell state & biases: cells (grp + 8rr, j0 + cc), j0 = 8wlo+2tg.
    const int j0 = 8 * wlo + 2 * tg;
    float bia[4][2];
#pragma unroll
    for (int g = 0; g < 4; g++) {
        bia[g][0] = bih[g * 64 + j0]     + bhh[g * 64 + j0];
        bia[g][1] = bih[g * 64 + j0 + 1] + bhh[g * 64 + j0 + 1];
    }
    float cst[2][2] = {{0.f, 0.f}, {0.f, 0.f}};

    // ── prologue: zero both h buffers; stage x(0), x(1); pre-GEMM x(0).
    for (int i = tid; i < 2 * BC * XS / 2; i += NT) ((unsigned*)sh)[i] = 0u;
    if (!isR) {
        if (role) wait_prog(prog, 2);
#pragma unroll
        for (int tt = 0; tt < 2; tt++) {
            uint2 r;
            if (role == 0) {
                const float4 v = *(const float4*)&x[((size_t)(b0 + sb) * SEQ + tt) * HID + sj];
                r.x = h2pack(v.x, v.y);
                r.y = h2pack(v.z, v.w);
            } else {
                r = *(const uint2*)&g_h1[((size_t)(b0 + sb) * SEQ + tt) * HID + sj];
            }
            *(uint2*)&sx[tt][sb * XS + sj] = r;
        }
    }
    __syncthreads();

    // X-warp GEMM macro: sx[buf] @ w_ih -> sxp[buf] (one float4 per lane).
#define XGEMM(buf)                                                            \
    {                                                                         \
        float d[4][4];                                                        \
        _Pragma("unroll")                                                     \
        for (int nn = 0; nn < 4; nn++)                                        \
            _Pragma("unroll")                                                 \
            for (int i = 0; i < 4; i++) d[nn][i] = 0.0f;                      \
        _Pragma("unroll")                                                     \
        for (int kk = 0; kk < 4; kk++) {                                      \
            const int ko = 16 * kk + 2 * tg;                                  \
            const unsigned a0 = *(const unsigned*)&sx[buf][grp * XS + ko];    \
            const unsigned a1 = *(const unsigned*)&sx[buf][(grp + 8) * XS + ko]; \
            const unsigned a2 = *(const unsigned*)&sx[buf][grp * XS + ko + 8]; \
            const unsigned a3 = *(const unsigned*)&sx[buf][(grp + 8) * XS + ko + 8]; \
            _Pragma("unroll")                                                 \
            for (int nn = 0; nn < 4; nn++)                                    \
                mmah(d[nn], a0, a1, a2, a3, bw[kk][nn][0], bw[kk][nn][1]);    \
        }                                                                     \
        _Pragma("unroll")                                                     \
        for (int nn = 0; nn < 4; nn++)                                        \
            sxp[buf][wlo][nn][lane] =                                         \
                make_float4(d[nn][0], d[nn][1], d[nn][2], d[nn][3]);          \
    }

    if (!isR) XGEMM(0);
    __syncthreads();

    for (int t = 0; t < SEQ; t++) {
        const int cur = t & 1, nb = cur ^ 1;

        if (isR) {
            // ── R: init accumulators with x-partials, add h @ w_hh.
            float d[4][4];
#pragma unroll
            for (int nn = 0; nn < 4; nn++) {
                const float4 v = sxp[cur][wlo][nn][lane];
                d[nn][0] = v.x; d[nn][1] = v.y; d[nn][2] = v.z; d[nn][3] = v.w;
            }
#pragma unroll
            for (int kk = 0; kk < 4; kk++) {
                const int ko = 16 * kk + 2 * tg;
                const unsigned a0 = *(const unsigned*)&sh[cur][grp * XS + ko];
                const unsigned a1 = *(const unsigned*)&sh[cur][(grp + 8) * XS + ko];
                const unsigned a2 = *(const unsigned*)&sh[cur][grp * XS + ko + 8];
                const unsigned a3 = *(const unsigned*)&sh[cur][(grp + 8) * XS + ko + 8];
#pragma unroll
                for (int nn = 0; nn < 4; nn++)
                    mmah(d[nn], a0, a1, a2, a3, bw[kk][nn][0], bw[kk][nn][1]);
            }
            // ── register-resident fp32 cell update: 4 cells/thread.
#pragma unroll
            for (int rr = 0; rr < 2; rr++) {
                float h2[2];
#pragma unroll
                for (int cc = 0; cc < 2; cc++) {
                    const int di = 2 * rr + cc;
                    const float iv = sig_fast(d[0][di] + bia[0][cc]);
                    const float fv = sig_fast(d[1][di] + bia[1][cc]);
                    const float gv = tanha(d[2][di] + bia[2][cc]);
                    const float ov = sig_fast(d[3][di] + bia[3][cc]);
                    float& cr = cst[rr][cc];
                    cr = fv * cr + iv * gv;
                    h2[cc] = ov * tanha(cr);
                }
                const int row = grp + 8 * rr;
                const unsigned hp = h2pack(h2[0], h2[1]);
                *(unsigned*)&sh[nb][row * XS + j0] = hp;
                if (role == 0)
                    *(unsigned*)&g_h1[((size_t)(b0 + row) * SEQ + t) * HID + j0] = hp;
            }
        } else {
            // ── X: poll (consumer), prefetch x(t+2), GEMM x(t+1), stage.
            if (role && (t & (PUB - 1)) == 0) {
                int need = t + PUB + 2; if (need > SEQ) need = SEQ;
                wait_prog(prog, need);
            }
            uint2 r;
            if (t + 2 < SEQ) {
                if (role == 0) {
                    const float4 v = *(const float4*)&x[((size_t)(b0 + sb) * SEQ + (t + 2)) * HID + sj];
                    r.x = h2pack(v.x, v.y);
                    r.y = h2pack(v.z, v.w);
                } else {
                    r = *(const uint2*)&g_h1[((size_t)(b0 + sb) * SEQ + (t + 2)) * HID + sj];
                }
            }
            if (t + 1 < SEQ) XGEMM(nb);
            if (t + 2 < SEQ)
                *(uint2*)&sx[cur][sb * XS + sj] = r;
        }

        // ── publish: R threads drain h1 STGs before the barrier.
        const bool pub = (role == 0) && (((t + 1) & (PUB - 1)) == 0);
        if (pub && isR) __threadfence();
        __syncthreads();
        if (pub && tid == 0)
            asm volatile("st.global.relaxed.gpu.b32 [%0], %1;"
                         :: "l"(prog), "r"(t + 1) : "memory");
    }

    // Fused FC head (layer-1 CTAs): final h is in sh[0].
    if (role == 1) {
        float v = fcw[lane] * __half2float(sh[0][w * XS + lane])
                + fcw[lane + 32] * __half2float(sh[0][w * XS + lane + 32]);
#pragma unroll
        for (int off = 16; off; off >>= 1)
            v += __shfl_down_sync(0xffffffffu, v, off);
        if (lane == 0) out[b0 + w] = v + fcb[0];
    }
#undef XGEMM
}

extern "C" void kernel_launch(void* const* d_in, const int* in_sizes, int n_in,
                              void* d_out, int out_size)
{
    const float* x     = (const float*)d_in[0];
    const float* w_ih0 = (const float*)d_in[1];
    const float* w_hh0 = (const float*)d_in[2];
    const float* b_ih0 = (const float*)d_in[3];
    const float* b_hh0 = (const float*)d_in[4];
    const float* w_ih1 = (const float*)d_in[5];
    const float* w_hh1 = (const float*)d_in[6];
    const float* b_ih1 = (const float*)d_in[7];
    const float* b_hh1 = (const float*)d_in[8];
    const float* fc_w  = (const float*)d_in[9];
    const float* fc_b  = (const float*)d_in[10];
    float* out = (float*)d_out;

    init_flags<<<1, 64>>>();
    lstm2_kernel<<<2 * NCHUNK, NT>>>(x,
                                     w_ih0, w_hh0, b_ih0, b_hh0,
                                     w_ih1, w_hh1, b_ih1, b_hh1,
                                     fc_w, fc_b, out);
}